// round 3
// baseline (speedup 1.0000x reference)
#include <cuda_runtime.h>
#include <cuda_bf16.h>

// SPU activation bounds (RIAI SPU-Trainable). The reference's (bs,n,n+1)
// "matrices" are diagonal + bias, so the whole backsubstitution reduces to an
// elementwise map:
//   al = lw * (lw>0 ? l : u) + lb
//   au = uw * (uw>0 ? u : l) + ub
// with (lw,lb,uw,ub) from the negative/positive/crossing SPU bound logic
// (crossing lower/upper need a fixed 20-step bisection).

__device__ __forceinline__ float fsigmoid(float x) {
    return 1.0f / (1.0f + __expf(-x));
}

// spu(x): x>=0 -> x^2 - 0.5 ; x<0 -> sigmoid(-x) - 1 = 1/(1+e^x) - 1
__device__ __forceinline__ float fspu(float x) {
    float ex  = __expf(x);
    float neg = 1.0f / (1.0f + ex) - 1.0f;
    float pos = x * x - 0.5f;
    return (x >= 0.0f) ? pos : neg;
}

// spu'(x): x<=-50 -> 0 ; x>=0 -> 2x ; else -0.5/(cosh(x)+1)
__device__ __forceinline__ float fspu_grad(float x) {
    float ex  = __expf(x);
    float ch  = 0.5f * (ex + 1.0f / ex);
    float neg = -0.5f / (ch + 1.0f);
    float g   = (x >= 0.0f) ? (2.0f * x) : neg;
    return (x <= -50.0f) ? 0.0f : g;
}

__device__ __forceinline__ void fspu_tangent(float x0, float& a, float& b) {
    a = fspu_grad(x0);
    b = fspu(x0) - a * x0;
}

// (spu(x)+0.5)/x with the reference's masking: "normal" lanes are
// x<=-1e-5 or x>0; otherwise return -0.25.
__device__ __forceinline__ float fspu_shifted_over_x(float x) {
    bool normal = (x <= -1e-5f) || (x > 0.0f);
    float sx = normal ? x : 1.0f;
    float v  = (fspu(sx) + 0.5f) / sx;
    return normal ? v : -0.25f;
}

__global__ void __launch_bounds__(128)
spu_bounds_kernel(const float* __restrict__ l_in,
                  const float* __restrict__ u_in,
                  const float* __restrict__ tl_raw,
                  const float* __restrict__ tu_raw,
                  float2* __restrict__ out,
                  int n_total)
{
    int i = blockIdx.x * blockDim.x + threadIdx.x;
    if (i >= n_total) return;

    float l = l_in[i];
    float u = u_in[i];
    float tl = fsigmoid(4.0f * tl_raw[i]);
    float tu = fsigmoid(4.0f * tu_raw[i]);

    float yl = fspu(l);
    float yu = fspu(u);

    // endpoint (secant) line
    float ea = (yu - yl) / (u - l + 1e-8f);
    float eb = yl - l * ea;

    float lw, lb, uw, ub;

    if (u <= 0.0f) {
        // ---- negative branch: lower = secant, upper = tangent at tu-point
        float a, b;
        fspu_tangent(l * (1.0f - tu) + u * tu, a, b);
        lw = ea; lb = eb;
        uw = a;  ub = b;
    } else if (l >= 0.0f) {
        // ---- positive branch: lower = tangent at tl-point, upper = secant
        float a, b;
        fspu_tangent(l * (1.0f - tl) + u * tl, a, b);
        lw = a;  lb = b;
        uw = ea; ub = eb;
    } else {
        // ---- crossing branch (l < 0 < u)

        // Upper bound: bisection for largest tangent point c in [l, 0] whose
        // tangent still covers (u, spu(u)).
        float req = yu;              // spu(u)
        float bl = l, br = 0.0f;
        #pragma unroll
        for (int it = 0; it < 20; ++it) {
            float c = 0.5f * (bl + br);
            float a, b;
            fspu_tangent(c, a, b);
            bool covers = (a * u + b) >= req;
            bl = covers ? c : bl;
            br = covers ? br : c;
        }
        float u_end = bl;

        float ua, ub_;
        fspu_tangent(l * (1.0f - tu) + u_end * tu, ua, ub_);
        bool not_cov = (ua * u + ub_) <= yu;      // spu(uc) == yu here
        uw = not_cov ? ea : ua;
        ub = not_cov ? eb : ub_;

        // Lower bound: tangent at tl-point if tl past the zero-crossing
        // threshold, else the "steep" parabola-matched line with b = -0.5.
        float den = u - l;                        // > 0 for crossing
        float threshold = -l / ((den == 0.0f) ? 1.0f : den);
        bool is_normal = (tl >= threshold);

        float nla, nlb;
        fspu_tangent(l * (1.0f - tl) + u * tl, nla, nlb);

        float steep    = fspu_shifted_over_x(l);
        float safe_thr = (threshold == 0.0f) ? 1.0f : threshold;
        float r        = tl / safe_thr;
        float wa       = steep * (1.0f - r * r);

        lw = is_normal ? nla : wa;
        lb = is_normal ? nlb : -0.5f;
    }

    // Diagonal backsubstitution (collapsed _substitute):
    float al = lw * ((lw > 0.0f) ? l : u) + lb;
    float au = uw * ((uw > 0.0f) ? u : l) + ub;

    out[i] = make_float2(al, au);
}

extern "C" void kernel_launch(void* const* d_in, const int* in_sizes, int n_in,
                              void* d_out, int out_size)
{
    const float* l  = (const float*)d_in[0];
    const float* u  = (const float*)d_in[1];
    const float* tl = (const float*)d_in[2];
    const float* tu = (const float*)d_in[3];
    float2* out = (float2*)d_out;

    int n = in_sizes[0];               // 64 * 1024 = 65536 elements
    const int threads = 128;
    int blocks = (n + threads - 1) / threads;

    spu_bounds_kernel<<<blocks, threads>>>(l, u, tl, tu, out, n);
}